// round 8
// baseline (speedup 1.0000x reference)
#include <cuda_runtime.h>
#include <cuda_bf16.h>
#include <math.h>

// Problem constants
#define BB 8
#define NN 256
#define DD 384
#define LL 6
#define HH 8
#define FFD 1536
#define TT 4
#define DH 48          // DD / HH
#define NM1 517        // TT + 1 + 2*NN
#define SS 1034        // 2 * NM1
#define MM (BB * SS)   // 8272 rows

// ---------------------------------------------------------------------------
// Scratch (device globals; no allocation allowed)
// ---------------------------------------------------------------------------
__device__ float g_src[MM * DD];
__device__ float g_src2[MM * DD];
__device__ float g_q[MM * DD];
__device__ float g_k[MM * DD];
__device__ float g_v[MM * DD];
__device__ float g_t1[MM * DD];
__device__ float g_ff[MM * FFD];
__device__ float g_coords[MM * 3];

// inv_freq[j] = 10000^(-j/8), j = 0..7 (computed in double, rounded to float)
__constant__ float c_invfreq[8] = {
    1.0000000000000000e+00f, 3.1622776601683794e-01f,
    1.0000000000000001e-01f, 3.1622776601683791e-02f,
    1.0000000000000000e-02f, 3.1622776601683794e-03f,
    1.0000000000000002e-03f, 3.1622776601683794e-04f
};

// ---------------------------------------------------------------------------
// Build src = concat([state_m1, hand_m1, head_m1, tok_m1, state_t, hand_t, head_t, tok_t])
// ---------------------------------------------------------------------------
__global__ void build_src_kernel(
    const float* __restrict__ hand_t, const float* __restrict__ head_t,
    const float* __restrict__ hand_m1, const float* __restrict__ head_m1,
    const float* __restrict__ state_t, const float* __restrict__ state_m1,
    const float* __restrict__ tokens_m1, const float* __restrict__ tokens_t,
    float* __restrict__ src)
{
    int i = blockIdx.x * blockDim.x + threadIdx.x;
    if (i >= BB * SS * DD) return;
    int d = i % DD;
    int s = (i / DD) % SS;
    int b = i / (DD * SS);

    int half = (s >= NM1);
    int sl = half ? (s - NM1) : s;   // 0..516 within half
    const float* statep = half ? state_t : state_m1;
    const float* handp  = half ? hand_t  : hand_m1;
    const float* headp  = half ? head_t  : head_m1;
    const float* tokp   = half ? tokens_t : tokens_m1;

    float val;
    if (sl == 0)                val = statep[b * DD + d];
    else if (sl < 1 + NN)       val = handp[((size_t)b * NN + (sl - 1)) * DD + d];
    else if (sl < 1 + 2 * NN)   val = headp[((size_t)b * NN + (sl - 1 - NN)) * DD + d];
    else                        val = tokp[(sl - 1 - 2 * NN) * DD + d];   // broadcast over b
    src[i] = val;
}

__global__ void build_coords_kernel(
    const float* __restrict__ ch_t, const float* __restrict__ che_t,
    const float* __restrict__ ch_m1, const float* __restrict__ che_m1,
    const float* __restrict__ tr_t, const float* __restrict__ tr_m1,
    float* __restrict__ coords)
{
    int i = blockIdx.x * blockDim.x + threadIdx.x;
    if (i >= BB * SS * 3) return;
    int a = i % 3;
    int s = (i / 3) % SS;
    int b = i / (3 * SS);

    int half = (s >= NM1);
    int sl = half ? (s - NM1) : s;
    const float* trp   = half ? tr_t : tr_m1;
    const float* handp = half ? ch_t : ch_m1;
    const float* headp = half ? che_t : che_m1;

    float val;
    if (sl == 0 || sl >= 1 + 2 * NN) val = trp[b * 3 + a];
    else if (sl < 1 + NN)            val = handp[((size_t)b * NN + (sl - 1)) * 3 + a];
    else                             val = headp[((size_t)b * NN + (sl - 1 - NN)) * 3 + a];
    coords[i] = val;
}

// ---------------------------------------------------------------------------
// fp32 GEMM core: C[M, Nout] = A[M, K] @ W[Nout, K]^T + bias, optional GELU.
// BM=128, BN=64, BK=16, 256 threads, 8x4 register tile per thread.
// Register-staged global loads + ping-pong smem (ONE barrier per k-tile).
// K multiple of 16, Nout multiple of 64. M bounds-checked.
// ---------------------------------------------------------------------------
#define GBM 128
#define GBN 64
#define GBK 16
#define APITCH (GBM + 4)   // keeps float4 alignment, avoids conflicts
#define WPITCH (GBN + 4)

__device__ __forceinline__ void gemm_core(
    const float* __restrict__ A, const float* __restrict__ W,
    const float* __restrict__ bias, float* __restrict__ C,
    int Mtot, int Nout, int K, int doGelu,
    int rowBase, int colBase)
{
    __shared__ float As[2][GBK][APITCH];
    __shared__ float Ws[2][GBK][WPITCH];

    const int tid = threadIdx.x;          // 0..255
    const int tr = tid >> 4;              // 0..15 -> rows tr*8 .. tr*8+7
    const int tc = tid & 15;              // 0..15 -> cols tc*4 .. tc*4+3

    float acc[8][4];
#pragma unroll
    for (int m = 0; m < 8; m++)
#pragma unroll
        for (int n = 0; n < 4; n++) acc[m][n] = 0.f;

    // A-tile: 128 rows x 4 float4 = 512 float4; 2 per thread.
    // W-tile: 64 rows x 4 float4 = 256 float4; 1 per thread.
    const int ar0 = tid >> 2;             // 0..63   (A load row, part 0)
    const int ar1 = ar0 + 64;             // 64..127 (A load row, part 1)
    const int ac4 = tid & 3;              // 0..3    (float4 index in k-slice)
    const int wr = tid >> 2;              // 0..63
    const int wc4 = tid & 3;              // 0..3

    const int g_ar0 = rowBase + ar0;
    const int g_ar1 = rowBase + ar1;
    const bool ok0 = (g_ar0 < Mtot);
    const bool ok1 = (g_ar1 < Mtot);
    const float* Ap0 = A + (size_t)(ok0 ? g_ar0 : 0) * K + ac4 * 4;
    const float* Ap1 = A + (size_t)(ok1 ? g_ar1 : 0) * K + ac4 * 4;
    const float* Wp  = W + (size_t)(colBase + wr) * K + wc4 * 4;

    // Prologue: load first k-tile into registers, store to buffer 0
    float4 ra0 = make_float4(0.f, 0.f, 0.f, 0.f);
    float4 ra1 = make_float4(0.f, 0.f, 0.f, 0.f);
    float4 rw;
    if (ok0) ra0 = *(const float4*)&Ap0[0];
    if (ok1) ra1 = *(const float4*)&Ap1[0];
    rw = *(const float4*)&Wp[0];

    As[0][ac4 * 4 + 0][ar0] = ra0.x;
    As[0][ac4 * 4 + 1][ar0] = ra0.y;
    As[0][ac4 * 4 + 2][ar0] = ra0.z;
    As[0][ac4 * 4 + 3][ar0] = ra0.w;
    As[0][ac4 * 4 + 0][ar1] = ra1.x;
    As[0][ac4 * 4 + 1][ar1] = ra1.y;
    As[0][ac4 * 4 + 2][ar1] = ra1.z;
    As[0][ac4 * 4 + 3][ar1] = ra1.w;
    Ws[0][wc4 * 4 + 0][wr] = rw.x;
    Ws[0][wc4 * 4 + 1][wr] = rw.y;
    Ws[0][wc4 * 4 + 2][wr] = rw.z;
    Ws[0][wc4 * 4 + 3][wr] = rw.w;
    __syncthreads();

    const int nTiles = K / GBK;
    int cur = 0;
    for (int t = 0; t < nTiles; t++) {
        // Stage next tile from global into registers (overlaps compute)
        const bool hasNext = (t + 1 < nTiles);
        if (hasNext) {
            int koff = (t + 1) * GBK;
            if (ok0) ra0 = *(const float4*)&Ap0[koff];
            if (ok1) ra1 = *(const float4*)&Ap1[koff];
            rw = *(const float4*)&Wp[koff];
        }

        // Compute from current buffer
#pragma unroll
        for (int kk = 0; kk < GBK; kk++) {
            float4 a0 = *(const float4*)&As[cur][kk][tr * 8];
            float4 a1 = *(const float4*)&As[cur][kk][tr * 8 + 4];
            float4 b0 = *(const float4*)&Ws[cur][kk][tc * 4];
            float ra[8] = {a0.x, a0.y, a0.z, a0.w, a1.x, a1.y, a1.z, a1.w};
            float rb[4] = {b0.x, b0.y, b0.z, b0.w};
#pragma unroll
            for (int m = 0; m < 8; m++)
#pragma unroll
                for (int n = 0; n < 4; n++) acc[m][n] += ra[m] * rb[n];
        }

        if (hasNext) {
            int nxt = cur ^ 1;
            // Writing the other buffer: no reader of it can exist past the
            // barrier of the previous iteration, so no pre-store sync needed.
            As[nxt][ac4 * 4 + 0][ar0] = ra0.x;
            As[nxt][ac4 * 4 + 1][ar0] = ra0.y;
            As[nxt][ac4 * 4 + 2][ar0] = ra0.z;
            As[nxt][ac4 * 4 + 3][ar0] = ra0.w;
            As[nxt][ac4 * 4 + 0][ar1] = ra1.x;
            As[nxt][ac4 * 4 + 1][ar1] = ra1.y;
            As[nxt][ac4 * 4 + 2][ar1] = ra1.z;
            As[nxt][ac4 * 4 + 3][ar1] = ra1.w;
            Ws[nxt][wc4 * 4 + 0][wr] = rw.x;
            Ws[nxt][wc4 * 4 + 1][wr] = rw.y;
            Ws[nxt][wc4 * 4 + 2][wr] = rw.z;
            Ws[nxt][wc4 * 4 + 3][wr] = rw.w;
            __syncthreads();
            cur = nxt;
        }
    }

    // Epilogue: bias (+ optional exact GELU), vectorized store
    float4 bv = *(const float4*)&bias[colBase + tc * 4];
#pragma unroll
    for (int m = 0; m < 8; m++) {
        int gr = rowBase + tr * 8 + m;
        if (gr >= Mtot) continue;
        float4 o;
        o.x = acc[m][0] + bv.x;
        o.y = acc[m][1] + bv.y;
        o.z = acc[m][2] + bv.z;
        o.w = acc[m][3] + bv.w;
        if (doGelu) {
            o.x = 0.5f * o.x * (1.f + erff(o.x * 0.70710678118654752f));
            o.y = 0.5f * o.y * (1.f + erff(o.y * 0.70710678118654752f));
            o.z = 0.5f * o.z * (1.f + erff(o.z * 0.70710678118654752f));
            o.w = 0.5f * o.w * (1.f + erff(o.w * 0.70710678118654752f));
        }
        *(float4*)&C[(size_t)gr * Nout + colBase + tc * 4] = o;
    }
}

__global__ void __launch_bounds__(256)
gemm_bias_kernel(const float* __restrict__ A, const float* __restrict__ W,
                 const float* __restrict__ bias, float* __restrict__ C,
                 int Mtot, int Nout, int K, int doGelu)
{
    gemm_core(A, W, bias, C, Mtot, Nout, K, doGelu,
              blockIdx.y * GBM, blockIdx.x * GBN);
}

// Fused Q/K/V projection: blockIdx.z selects which of the three GEMMs.
__global__ void __launch_bounds__(256)
gemm_qkv_kernel(const float* __restrict__ A,
                const float* __restrict__ Wq, const float* __restrict__ bq,
                const float* __restrict__ Wk, const float* __restrict__ bk,
                const float* __restrict__ Wv, const float* __restrict__ bv,
                float* __restrict__ Cq, float* __restrict__ Ck, float* __restrict__ Cv,
                int Mtot, int Nout, int K)
{
    const float* W;
    const float* bias;
    float* C;
    if (blockIdx.z == 0)      { W = Wq; bias = bq; C = Cq; }
    else if (blockIdx.z == 1) { W = Wk; bias = bk; C = Ck; }
    else                      { W = Wv; bias = bv; C = Cv; }
    gemm_core(A, W, bias, C, Mtot, Nout, K, 0,
              blockIdx.y * GBM, blockIdx.x * GBN);
}

// ---------------------------------------------------------------------------
// Rotary PE 3D, applied in-place to q and k. One thread per (b, s, h).
// dh=48, split into 3 axes of 16, each with half=8 rotation pairs.
// inv_freq from constant table (no powf).
// ---------------------------------------------------------------------------
__global__ void rotary_kernel(float* __restrict__ q, float* __restrict__ k,
                              const float* __restrict__ coords)
{
    int u = blockIdx.x * blockDim.x + threadIdx.x;
    if (u >= BB * SS * HH) return;
    int h = u % HH;
    int bs = u / HH;
    const float* cp = coords + (size_t)bs * 3;
    float* qp = q + (size_t)bs * DD + h * DH;
    float* kp = k + (size_t)bs * DD + h * DH;

#pragma unroll
    for (int a = 0; a < 3; a++) {
        float ca = cp[a];
#pragma unroll
        for (int j = 0; j < 8; j++) {
            float ang = ca * c_invfreq[j];
            float sv, cv;
            sincosf(ang, &sv, &cv);
            float q1 = qp[a * 16 + j], q2 = qp[a * 16 + 8 + j];
            qp[a * 16 + j]     = q1 * cv - q2 * sv;
            qp[a * 16 + 8 + j] = q1 * sv + q2 * cv;
            float k1 = kp[a * 16 + j], k2 = kp[a * 16 + 8 + j];
            kp[a * 16 + j]     = k1 * cv - k2 * sv;
            kp[a * 16 + 8 + j] = k1 * sv + k2 * cv;
        }
    }
}

// ---------------------------------------------------------------------------
// Flash-style attention. One thread per query row; block = 128 queries of one
// (b, h). K/V streamed through shared memory in tiles of 64 keys.
// Block mask: queries < NM1 attend only to keys < NM1 (everything else full).
// Block-level early exit: blocks fully inside the first half stop at NM1.
// Running-max rescale only on (rare) max updates.
// ---------------------------------------------------------------------------
__global__ void __launch_bounds__(128)
attn_kernel(const float* __restrict__ q, const float* __restrict__ k,
            const float* __restrict__ v, float* __restrict__ o)
{
    const int b = blockIdx.z;
    const int h = blockIdx.y;
    const int qi = blockIdx.x * 128 + threadIdx.x;

    __shared__ float Ks[64][48];
    __shared__ float Vs[64][48];

    // per-thread key limit: inactive threads get 0
    int lim = (qi < NM1) ? NM1 : ((qi < SS) ? SS : 0);
    // block-level key limit (uniform across block): if every query in this
    // block is in the first half, no thread ever reads keys >= NM1.
    const int blockLim = (blockIdx.x * 128 + 127 < NM1) ? NM1 : SS;

    float qr[48], acc[48];
    {
        int qs = (qi < SS) ? qi : (SS - 1);
        const float* qp = q + ((size_t)(b * SS + qs)) * DD + h * DH;
        const float scale = rsqrtf((float)DH);
#pragma unroll
        for (int d = 0; d < 48; d++) { qr[d] = qp[d] * scale; acc[d] = 0.f; }
    }
    float mval = -1e30f, lval = 0.f;

    for (int t0 = 0; t0 < blockLim; t0 += 64) {
        __syncthreads();
        // 64 rows x 12 float4 = 768 float4 per matrix; 128 threads -> 6 each
        for (int e = threadIdx.x; e < 64 * 12; e += 128) {
            int j = e / 12, q4 = e % 12;
            int kj = t0 + j;
            float4 kv = make_float4(0.f, 0.f, 0.f, 0.f);
            float4 vv = make_float4(0.f, 0.f, 0.f, 0.f);
            if (kj < SS) {
                size_t base = ((size_t)(b * SS + kj)) * DD + h * DH + q4 * 4;
                kv = *(const float4*)&k[base];
                vv = *(const float4*)&v[base];
            }
            *(float4*)&Ks[j][q4 * 4] = kv;
            *(float4*)&Vs[j][q4 * 4] = vv;
        }
        __syncthreads();

        if (t0 >= lim) continue;
        int jl = min(64, lim - t0);
        for (int j = 0; j < jl; j++) {
            float s = 0.f;
#pragma unroll
            for (int d = 0; d < 48; d++) s += qr[d] * Ks[j][d];
            if (s > mval) {
                float corr = expf(mval - s);
                lval *= corr;
#pragma unroll
                for (int d = 0; d < 48; d++) acc[d] *= corr;
                mval = s;
            }
            float p = expf(s - mval);
            lval += p;
#pragma unroll
            for (int d = 0; d < 48; d++) acc[d] += p * Vs[j][d];
        }
    }

    if (qi < SS) {
        float inv = 1.f / lval;
        float* op = o + ((size_t)(b * SS + qi)) * DD + h * DH;
#pragma unroll
        for (int d = 0; d < 48; d++) op[d] = acc[d] * inv;
    }
}

// ---------------------------------------------------------------------------
// out = LayerNorm(resid + x) * g + be   (one block of 128 threads per row, D=384)
// ---------------------------------------------------------------------------
__global__ void __launch_bounds__(128)
add_ln_kernel(const float* __restrict__ resid, const float* __restrict__ x,
              const float* __restrict__ g, const float* __restrict__ be,
              float* __restrict__ out)
{
    int row = blockIdx.x;
    const float* rp = resid + (size_t)row * DD;
    const float* xp = x + (size_t)row * DD;

    float vloc[3];
    float sum = 0.f, sumsq = 0.f;
#pragma unroll
    for (int i = 0; i < 3; i++) {
        int d = threadIdx.x + i * 128;
        float vv = rp[d] + xp[d];
        vloc[i] = vv;
        sum += vv;
        sumsq += vv * vv;
    }
#pragma unroll
    for (int off = 16; off > 0; off >>= 1) {
        sum += __shfl_down_sync(0xffffffffu, sum, off);
        sumsq += __shfl_down_sync(0xffffffffu, sumsq, off);
    }
    __shared__ float s1[4], s2[4];
    int wid = threadIdx.x >> 5, lid = threadIdx.x & 31;
    if (lid == 0) { s1[wid] = sum; s2[wid] = sumsq; }
    __syncthreads();
    if (threadIdx.x == 0) {
        float a = 0.f, c = 0.f;
        for (int w = 0; w < 4; w++) { a += s1[w]; c += s2[w]; }
        s1[0] = a; s2[0] = c;
    }
    __syncthreads();
    float mean = s1[0] * (1.f / DD);
    float var = s2[0] * (1.f / DD) - mean * mean;
    float rstd = rsqrtf(var + 1e-5f);
#pragma unroll
    for (int i = 0; i < 3; i++) {
        int d = threadIdx.x + i * 128;
        out[(size_t)row * DD + d] = (vloc[i] - mean) * rstd * g[d] + be[d];
    }
}

// ---------------------------------------------------------------------------
// Output: src[:, -T:, :]  -> out[B, T, D]
// ---------------------------------------------------------------------------
__global__ void out_copy_kernel(const float* __restrict__ src, float* __restrict__ out)
{
    int i = blockIdx.x * blockDim.x + threadIdx.x;
    if (i >= BB * TT * DD) return;
    int d = i % DD;
    int t = (i / DD) % TT;
    int b = i / (DD * TT);
    out[i] = src[((size_t)(b * SS + (SS - TT + t))) * DD + d];
}

// ---------------------------------------------------------------------------
// Launcher
// ---------------------------------------------------------------------------
extern "C" void kernel_launch(void* const* d_in, const int* in_sizes, int n_in,
                              void* d_out, int out_size)
{
    const float* hand_t   = (const float*)d_in[0];
    const float* head_t   = (const float*)d_in[1];
    const float* hand_m1  = (const float*)d_in[2];
    const float* head_m1  = (const float*)d_in[3];
    const float* c_hand_t = (const float*)d_in[4];
    const float* c_head_t = (const float*)d_in[5];
    const float* c_hand_m1= (const float*)d_in[6];
    const float* c_head_m1= (const float*)d_in[7];
    const float* state_t  = (const float*)d_in[8];
    const float* state_m1 = (const float*)d_in[9];
    const float* trans_t  = (const float*)d_in[10];
    const float* trans_m1 = (const float*)d_in[11];
    const float* tokens_m1= (const float*)d_in[12];
    const float* tokens_t = (const float*)d_in[13];
    const float* Wq = (const float*)d_in[14];
    const float* bq = (const float*)d_in[15];
    const float* Wk = (const float*)d_in[16];
    const float* bk = (const float*)d_in[17];
    const float* Wv = (const float*)d_in[18];
    const float* bv = (const float*)d_in[19];
    const float* Wo = (const float*)d_in[20];
    const float* bo = (const float*)d_in[21];
    const float* W1 = (const float*)d_in[22];
    const float* b1 = (const float*)d_in[23];
    const float* W2 = (const float*)d_in[24];
    const float* b2 = (const float*)d_in[25];
    const float* g1 = (const float*)d_in[26];
    const float* be1= (const float*)d_in[27];
    const float* g2 = (const float*)d_in[28];
    const float* be2= (const float*)d_in[29];

    float *p_src, *p_src2, *p_q, *p_k, *p_v, *p_t1, *p_ff, *p_coords;
    cudaGetSymbolAddress((void**)&p_src, g_src);
    cudaGetSymbolAddress((void**)&p_src2, g_src2);
    cudaGetSymbolAddress((void**)&p_q, g_q);
    cudaGetSymbolAddress((void**)&p_k, g_k);
    cudaGetSymbolAddress((void**)&p_v, g_v);
    cudaGetSymbolAddress((void**)&p_t1, g_t1);
    cudaGetSymbolAddress((void**)&p_ff, g_ff);
    cudaGetSymbolAddress((void**)&p_coords, g_coords);

    build_src_kernel<<<(BB * SS * DD + 255) / 256, 256>>>(
        hand_t, head_t, hand_m1, head_m1, state_t, state_m1, tokens_m1, tokens_t, p_src);
    build_coords_kernel<<<(BB * SS * 3 + 255) / 256, 256>>>(
        c_hand_t, c_head_t, c_hand_m1, c_head_m1, trans_t, trans_m1, p_coords);

    dim3 gD(DD / GBN, (MM + GBM - 1) / GBM);        // (6, 65)
    dim3 gQKV(DD / GBN, (MM + GBM - 1) / GBM, 3);   // (6, 65, 3)
    dim3 gFF(FFD / GBN, (MM + GBM - 1) / GBM);      // (24, 65)
    dim3 gAttn((SS + 127) / 128, HH, BB);           // (9, 8, 8)

    for (int l = 0; l < LL; l++) {
        const float* Wq_l = Wq + (size_t)l * DD * DD;
        const float* bq_l = bq + (size_t)l * DD;
        const float* Wk_l = Wk + (size_t)l * DD * DD;
        const float* bk_l = bk + (size_t)l * DD;
        const float* Wv_l = Wv + (size_t)l * DD * DD;
        const float* bv_l = bv + (size_t)l * DD;
        const float* Wo_l = Wo + (size_t)l * DD * DD;
        const float* bo_l = bo + (size_t)l * DD;
        const float* W1_l = W1 + (size_t)l * FFD * DD;
        const float* b1_l = b1 + (size_t)l * FFD;
        const float* W2_l = W2 + (size_t)l * DD * FFD;
        const float* b2_l = b2 + (size_t)l * DD;
        const float* g1_l = g1 + (size_t)l * DD;
        const float* be1_l= be1 + (size_t)l * DD;
        const float* g2_l = g2 + (size_t)l * DD;
        const float* be2_l= be2 + (size_t)l * DD;

        gemm_qkv_kernel<<<gQKV, 256>>>(p_src, Wq_l, bq_l, Wk_l, bk_l, Wv_l, bv_l,
                                       p_q, p_k, p_v, MM, DD, DD);

        rotary_kernel<<<(BB * SS * HH + 127) / 128, 128>>>(p_q, p_k, p_coords);

        attn_kernel<<<gAttn, 128>>>(p_q, p_k, p_v, p_t1);

        gemm_bias_kernel<<<gD, 256>>>(p_t1, Wo_l, bo_l, p_q, MM, DD, DD, 0);

        add_ln_kernel<<<MM, 128>>>(p_src, p_q, g1_l, be1_l, p_src2);

        gemm_bias_kernel<<<gFF, 256>>>(p_src2, W1_l, b1_l, p_ff, MM, FFD, DD, 1);
        gemm_bias_kernel<<<gD, 256>>>(p_ff, W2_l, b2_l, p_k, MM, DD, FFD, 0);

        add_ln_kernel<<<MM, 128>>>(p_src2, p_k, g2_l, be2_l, p_src);
    }

    out_copy_kernel<<<(BB * TT * DD + 255) / 256, 256>>>(p_src, (float*)d_out);
}